// round 15
// baseline (speedup 1.0000x reference)
#include <cuda_runtime.h>
#include <cuda_fp16.h>
#include <math.h>
#include <stdint.h>

#define DMODEL 1024
#define SEQ    2048
#define NB     2
#define NH     16
#define HD     64
#define MTOT   (NB*SEQ)          // 4096
#define WN     (DMODEL*DMODEL)

// ---------------- scratch (__device__ globals; allocation-free rule) --------
__device__ __align__(16) __half g_xs1[MTOT*DMODEL];
__device__ __align__(16) __half g_xs2[MTOT*DMODEL];
__device__ __align__(16) __half g_as1[MTOT*DMODEL];
__device__ __align__(16) __half g_as2[MTOT*DMODEL];
__device__ __align__(16) __half g_w1[4*WN];          // single fp16 weights
__device__ __align__(16) __half g_q1[MTOT*DMODEL];
__device__ __align__(16) __half g_q2[MTOT*DMODEL];
__device__ __align__(16) __half g_k1[MTOT*DMODEL];   // single fp16 K
__device__ __align__(16) __half g_v1[MTOT*DMODEL];   // single fp16 V
__device__ __align__(16) float2 g_rope[SEQ*32];      // (cos, sin) per (t, d)

// ---------------- PTX helpers ----------------------------------------------
__device__ __forceinline__ uint32_t smem_u32(const void* p) {
    uint32_t a;
    asm("{ .reg .u64 t; cvta.to.shared.u64 t, %1; cvt.u32.u64 %0, t; }"
        : "=r"(a) : "l"(p));
    return a;
}
__device__ __forceinline__ void cp16(uint32_t dst, const void* src) {
    asm volatile("cp.async.cg.shared.global [%0], [%1], 16;" :: "r"(dst), "l"(src));
}
#define CP_COMMIT()  asm volatile("cp.async.commit_group;" ::: "memory")
#define CP_WAIT(n)   asm volatile("cp.async.wait_group %0;" :: "n"(n) : "memory")

#define LDSM4(r, adr) \
    asm volatile("ldmatrix.sync.aligned.m8n8.x4.shared.b16 {%0,%1,%2,%3}, [%4];" \
        : "=r"((r)[0]), "=r"((r)[1]), "=r"((r)[2]), "=r"((r)[3]) : "r"(adr))
#define LDSM4T(r, adr) \
    asm volatile("ldmatrix.sync.aligned.m8n8.x4.trans.shared.b16 {%0,%1,%2,%3}, [%4];" \
        : "=r"((r)[0]), "=r"((r)[1]), "=r"((r)[2]), "=r"((r)[3]) : "r"(adr))

#define MMA_F16(c, a, b) \
    asm volatile("mma.sync.aligned.m16n8k16.row.col.f32.f16.f16.f32 " \
        "{%0,%1,%2,%3}, {%4,%5,%6,%7}, {%8,%9}, {%0,%1,%2,%3};" \
        : "+f"((c)[0]), "+f"((c)[1]), "+f"((c)[2]), "+f"((c)[3]) \
        : "r"((a)[0]), "r"((a)[1]), "r"((a)[2]), "r"((a)[3]), \
          "r"((b)[0]), "r"((b)[1]))

__device__ __forceinline__ uint32_t packh(float a, float b) {
    uint32_t r;
    asm("cvt.rn.f16x2.f32 %0, %1, %2;" : "=r"(r) : "f"(b), "f"(a));
    return r;
}
__device__ __forceinline__ void split2h(float a, float b, uint32_t& hi, uint32_t& lo) {
    hi = packh(a, b);
    float ah, bh;
    asm("{ .reg .f16 h0, h1; mov.b32 {h0, h1}, %2;"
        " cvt.f32.f16 %0, h0; cvt.f32.f16 %1, h1; }"
        : "=f"(ah), "=f"(bh) : "r"(hi));
    lo = packh(a - ah, b - bh);
}

// swizzles
#define SW128X(o) ((o) ^ (((o) >> 3) & 0x70))

// ---------------- small prep kernels ----------------------------------------
__global__ __launch_bounds__(256)
void rope_kernel()
{
    int i = blockIdx.x * blockDim.x + threadIdx.x;
    if (i >= SEQ*32) return;
    int t = i >> 5, d = i & 31;
    float invf = exp2f(-(float)d * 0.4152410118609203f);
    float sn, cs;
    sincosf((float)t * invf, &sn, &cs);
    g_rope[i] = make_float2(cs, sn);
}

__global__ __launch_bounds__(256)
void split_kernel(const float* __restrict__ s, __half* __restrict__ d1,
                  __half* __restrict__ d2, int n4)
{
    int i = blockIdx.x * blockDim.x + threadIdx.x;
    if (i >= n4) return;
    float4 v = ((const float4*)s)[i];
    uint32_t h0, l0, h1, l1;
    split2h(v.x, v.y, h0, l0);
    split2h(v.z, v.w, h1, l1);
    ((uint2*)d1)[i] = make_uint2(h0, h1);
    ((uint2*)d2)[i] = make_uint2(l0, l1);
}

__global__ __launch_bounds__(256)
void split_w_kernel(const float* __restrict__ wq, const float* __restrict__ wk,
                    const float* __restrict__ wv, const float* __restrict__ wo)
{
    int i = blockIdx.x * blockDim.x + threadIdx.x;
    if (i >= WN) return;
    int wsel = i / (WN/4);
    int off  = i - wsel * (WN/4);
    const float* src = (wsel == 0) ? wq : (wsel == 1) ? wk : (wsel == 2) ? wv : wo;
    float4 v = ((const float4*)src)[off];
    ((uint2*)(g_w1 + (size_t)wsel*WN))[off] =
        make_uint2(packh(v.x, v.y), packh(v.z, v.w));
}

// ---------------- mma.sync GEMM (round-13 inner loop, verbatim) -------------
#define TILE_BYTES 16384            // 128 rows * 128 B (64 fp16)
#define STAGE_BYTES (3*TILE_BYTES)  // A1, A2, B = 49152

__global__ __launch_bounds__(256, 2)
void gemm_mma(const __half* __restrict__ A1, const __half* __restrict__ A2,
              float* __restrict__ C, int qkv)
{
    extern __shared__ __align__(16) char sm[];
    const uint32_t sb = smem_u32(sm);
    const int tid = threadIdx.x;
    const int lane = tid & 31, wid = tid >> 5;
    const int wm = wid & 3, wn = wid >> 2;
    const int m0 = blockIdx.y << 7;
    const int nglob = blockIdx.x << 7;

    int wsel, n0, mode;
    __half *D1 = nullptr, *D2 = nullptr;
    if (qkv) {
        wsel = nglob >> 10;           // 0=Q,1=K,2=V
        n0   = nglob & 1023;
        mode = wsel + 1;
        D1 = (wsel == 0) ? g_q1 : (wsel == 1) ? g_k1 : g_v1;
        D2 = (wsel == 0) ? g_q2 : nullptr;
    } else {
        wsel = 3; n0 = nglob; mode = 0;
    }
    const __half* B1 = g_w1 + (size_t)wsel * WN;

    float acc[2][8][4];
#pragma unroll
    for (int mf = 0; mf < 2; ++mf)
#pragma unroll
        for (int nf = 0; nf < 8; ++nf)
#pragma unroll
            for (int j = 0; j < 4; ++j) acc[mf][nf][j] = 0.f;

    const int lrow = tid >> 3;
    const int lch  = tid & 7;
    uint32_t st_sw[4];
#pragma unroll
    for (int p = 0; p < 4; ++p)
        st_sw[p] = SW128X((uint32_t)(lrow + p*32) * 128 + (uint32_t)lch * 16);

    auto load_stage = [&](int t, int slot) {
        const int k0 = t << 6;
        const uint32_t base = sb + (uint32_t)slot * STAGE_BYTES;
#pragma unroll
        for (int tile = 0; tile < 3; ++tile) {
            const __half* S = (tile == 0) ? A1 : (tile == 1) ? A2 : B1;
            const int rb = (tile < 2) ? m0 : n0;
#pragma unroll
            for (int p = 0; p < 4; ++p)
                cp16(base + tile * TILE_BYTES + st_sw[p],
                     S + (size_t)(rb + lrow + p*32) * DMODEL + k0 + lch * 8);
        }
    };

    load_stage(0, 0); CP_COMMIT();

    const uint32_t a_row  = (uint32_t)(wm * 32) + (lane & 15);
    const uint32_t a_koff = (uint32_t)(lane >> 4) * 16;
    const uint32_t b_row  = (uint32_t)(wn * 64) + (lane & 7) + ((lane >> 4) & 1) * 8;
    const uint32_t b_koff = (uint32_t)((lane >> 3) & 1) * 16;

    for (int t = 0; t < 16; ++t) {
        CP_WAIT(0);
        __syncthreads();
        if (t < 15) { load_stage(t + 1, (t + 1) & 1); CP_COMMIT(); }

        const uint32_t buf = sb + (uint32_t)(t & 1) * STAGE_BYTES;
#pragma unroll
        for (int ks = 0; ks < 4; ++ks) {
            const uint32_t kbyte = (uint32_t)ks * 32;
            uint32_t A1f[2][4], A2f[2][4];
#pragma unroll
            for (int mf = 0; mf < 2; ++mf) {
                uint32_t o = (a_row + mf*16) * 128 + kbyte + a_koff;
                uint32_t adr = buf + SW128X(o);
                LDSM4(A1f[mf], adr);
                LDSM4(A2f[mf], adr + TILE_BYTES);
            }
#pragma unroll
            for (int nb = 0; nb < 4; ++nb) {
                uint32_t o = (b_row + nb*16) * 128 + kbyte + b_koff;
                uint32_t adr = buf + 2 * TILE_BYTES + SW128X(o);
                uint32_t rB[4];
                LDSM4(rB, adr);
                uint32_t b_a[2] = {rB[0], rB[1]}, b_b[2] = {rB[2], rB[3]};
#pragma unroll
                for (int mf = 0; mf < 2; ++mf) {
                    MMA_F16(acc[mf][2*nb],   A1f[mf], b_a);
                    MMA_F16(acc[mf][2*nb],   A2f[mf], b_a);
                    MMA_F16(acc[mf][2*nb+1], A1f[mf], b_b);
                    MMA_F16(acc[mf][2*nb+1], A2f[mf], b_b);
                }
            }
        }
    }

    // ---- epilogue ----
    const int g = lane >> 2, tg = lane & 3;
    if (mode == 1) {
#pragma unroll
        for (int mf = 0; mf < 2; ++mf)
#pragma unroll
            for (int rh = 0; rh < 2; ++rh) {
                int row = m0 + wm*32 + mf*16 + g + rh*8;
                const float2* rope = g_rope + (size_t)(row & (SEQ - 1)) * 32 + tg*2;
                size_t base = (size_t)row * DMODEL + n0 + wn*64;
#pragma unroll
                for (int nf = 0; nf < 4; ++nf) {
                    float o1[2], o2[2];
#pragma unroll
                    for (int bb = 0; bb < 2; ++bb) {
                        float2 cssn = rope[nf*8 + bb];
                        float v1 = acc[mf][nf][rh*2 + bb];
                        float v2 = acc[mf][nf+4][rh*2 + bb];
                        o1[bb] = (v1*cssn.x - v2*cssn.y) * 0.125f;
                        o2[bb] = (v2*cssn.x + v1*cssn.y) * 0.125f;
                    }
                    uint32_t h_, l_;
                    split2h(o1[0], o1[1], h_, l_);
                    *(uint32_t*)(D1 + base + nf*8 + tg*2) = h_;
                    *(uint32_t*)(D2 + base + nf*8 + tg*2) = l_;
                    split2h(o2[0], o2[1], h_, l_);
                    *(uint32_t*)(D1 + base + nf*8 + tg*2 + 32) = h_;
                    *(uint32_t*)(D2 + base + nf*8 + tg*2 + 32) = l_;
                }
            }
    } else if (mode == 2) {
#pragma unroll
        for (int mf = 0; mf < 2; ++mf)
#pragma unroll
            for (int rh = 0; rh < 2; ++rh) {
                int row = m0 + wm*32 + mf*16 + g + rh*8;
                const float2* rope = g_rope + (size_t)(row & (SEQ - 1)) * 32 + tg*2;
                size_t base = (size_t)row * DMODEL + n0 + wn*64;
#pragma unroll
                for (int nf = 0; nf < 4; ++nf) {
                    float o1[2], o2[2];
#pragma unroll
                    for (int bb = 0; bb < 2; ++bb) {
                        float2 cssn = rope[nf*8 + bb];
                        float v1 = acc[mf][nf][rh*2 + bb];
                        float v2 = acc[mf][nf+4][rh*2 + bb];
                        o1[bb] = v1*cssn.x - v2*cssn.y;
                        o2[bb] = v2*cssn.x + v1*cssn.y;
                    }
                    *(uint32_t*)(D1 + base + nf*8 + tg*2)      = packh(o1[0], o1[1]);
                    *(uint32_t*)(D1 + base + nf*8 + tg*2 + 32) = packh(o2[0], o2[1]);
                }
            }
    } else if (mode == 3) {
#pragma unroll
        for (int mf = 0; mf < 2; ++mf)
#pragma unroll
            for (int rh = 0; rh < 2; ++rh) {
                int row = m0 + wm*32 + mf*16 + g + rh*8;
                size_t base = (size_t)row * DMODEL + n0 + wn*64;
#pragma unroll
                for (int nf = 0; nf < 8; ++nf)
                    *(uint32_t*)(D1 + base + nf*8 + tg*2) =
                        packh(acc[mf][nf][rh*2], acc[mf][nf][rh*2+1]);
            }
    } else {
#pragma unroll
        for (int mf = 0; mf < 2; ++mf)
#pragma unroll
            for (int rh = 0; rh < 2; ++rh) {
                int row = m0 + wm*32 + mf*16 + g + rh*8;
                float* Crow = C + (size_t)row * DMODEL + n0 + wn*64;
#pragma unroll
                for (int nf = 0; nf < 8; ++nf)
                    *(float2*)(Crow + nf*8 + tg*2) =
                        make_float2(acc[mf][nf][rh*2], acc[mf][nf][rh*2 + 1]);
            }
    }
}

// ---------------- tensor-core flash attention (1 sync/iter pipeline) --------
#define ROWB 144
#define TB   (64*ROWB)      // 9216 per tile
#define STG  (2*TB)         // K1, V1 per stage = 18432

__global__ __launch_bounds__(128)
void attn_mma()
{
    extern __shared__ __align__(16) char sm[];
    const uint32_t sb = smem_u32(sm);
    const int tid = threadIdx.x, lane = tid & 31, w = tid >> 5;
    const int it = gridDim.x - 1 - blockIdx.x;
    const int h = blockIdx.y, b = blockIdx.z;
    const int i0 = it << 6;
    const size_t hoff = (size_t)h * HD;
    const int g = lane >> 2, tg = lane & 3;

#pragma unroll
    for (int p = 0; p < 4; ++p) {
        int id = tid + (p << 7);
        int row = id >> 3, ch = id & 7;
        size_t gi = (size_t)(b*SEQ + i0 + row)*DMODEL + hoff + ch*8;
        uint32_t dst = sb + row*ROWB + ch*16;
        cp16(dst,      g_q1 + gi);
        cp16(dst + TB, g_q2 + gi);
    }
    CP_COMMIT(); CP_WAIT(0); __syncthreads();

    uint32_t Q1f[4][4], Q2f[4][4];
    const uint32_t a_off = (uint32_t)(lane & 15)*ROWB + (uint32_t)(lane >> 4)*16;
#pragma unroll
    for (int kf = 0; kf < 4; ++kf) {
        uint32_t adr = sb + (uint32_t)(w*16)*ROWB + a_off + kf*32;
        LDSM4(Q1f[kf], adr);
        LDSM4(Q2f[kf], adr + TB);
    }
    __syncthreads();

    auto load_kv = [&](int jt) {
        const int j0 = jt << 6;
        const uint32_t base = sb + (uint32_t)(jt & 1)*STG;
#pragma unroll
        for (int p = 0; p < 4; ++p) {
            int id = tid + (p << 7);
            int row = id >> 3, ch = id & 7;
            size_t gi = (size_t)(b*SEQ + j0 + row)*DMODEL + hoff + ch*8;
            uint32_t dst = base + row*ROWB + ch*16;
            cp16(dst,      g_k1 + gi);
            cp16(dst + TB, g_v1 + gi);
        }
    };

    load_kv(0); CP_COMMIT();

    float mr[2] = {-1e30f, -1e30f}, lr[2] = {0.f, 0.f};
    float O[8][4];
#pragma unroll
    for (int nf = 0; nf < 8; ++nf)
#pragma unroll
        for (int j = 0; j < 4; ++j) O[nf][j] = 0.f;

    const int      b_nloc = (lane & 7) + ((lane >> 4) & 1)*8;
    const uint32_t b_koff = (uint32_t)((lane >> 3) & 1)*16;

    for (int jt = 0; jt <= it; ++jt) {
        CP_WAIT(0);            // stage jt resident
        __syncthreads();       // all warps done reading slot (jt+1)&1 (= jt-1)
        if (jt < it) { load_kv(jt + 1); CP_COMMIT(); }
        const uint32_t buf = sb + (uint32_t)(jt & 1)*STG;

        float S[8][4];
#pragma unroll
        for (int nf = 0; nf < 8; ++nf)
#pragma unroll
            for (int j = 0; j < 4; ++j) S[nf][j] = 0.f;

#pragma unroll
        for (int kf = 0; kf < 4; ++kf) {
            uint32_t K1f[8][2];
#pragma unroll
            for (int nb = 0; nb < 4; ++nb) {
                uint32_t adr = buf + (uint32_t)(nb*16 + b_nloc)*ROWB + kf*32 + b_koff;
                uint32_t r[4];
                LDSM4(r, adr);
                K1f[2*nb][0] = r[0]; K1f[2*nb][1] = r[1];
                K1f[2*nb+1][0] = r[2]; K1f[2*nb+1][1] = r[3];
            }
#pragma unroll
            for (int nf = 0; nf < 8; ++nf) {
                MMA_F16(S[nf], Q1f[kf], K1f[nf]);
                MMA_F16(S[nf], Q2f[kf], K1f[nf]);
            }
        }

        if (jt == it) {
            int r0 = w*16 + g;
#pragma unroll
            for (int nf = 0; nf < 8; ++nf)
#pragma unroll
                for (int j = 0; j < 2; ++j) {
                    int col = nf*8 + tg*2 + j;
                    if (col > r0)     S[nf][j]   = -1e30f;
                    if (col > r0 + 8) S[nf][j+2] = -1e30f;
                }
        }

        float mx0 = -1e30f, mx1 = -1e30f;
#pragma unroll
        for (int nf = 0; nf < 8; ++nf) {
            mx0 = fmaxf(mx0, fmaxf(S[nf][0], S[nf][1]));
            mx1 = fmaxf(mx1, fmaxf(S[nf][2], S[nf][3]));
        }
        mx0 = fmaxf(mx0, __shfl_xor_sync(0xffffffffu, mx0, 1));
        mx0 = fmaxf(mx0, __shfl_xor_sync(0xffffffffu, mx0, 2));
        mx1 = fmaxf(mx1, __shfl_xor_sync(0xffffffffu, mx1, 1));
        mx1 = fmaxf(mx1, __shfl_xor_sync(0xffffffffu, mx1, 2));
        float mn0 = fmaxf(mr[0], mx0), mn1 = fmaxf(mr[1], mx1);
        float c0 = __expf(mr[0] - mn0), c1 = __expf(mr[1] - mn1);
        float s0 = 0.f, s1 = 0.f;
#pragma unroll
        for (int nf = 0; nf < 8; ++nf) {
            S[nf][0] = __expf(S[nf][0] - mn0);
            S[nf][1] = __expf(S[nf][1] - mn0);
            S[nf][2] = __expf(S[nf][2] - mn1);
            S[nf][3] = __expf(S[nf][3] - mn1);
            s0 += S[nf][0] + S[nf][1];
            s1 += S[nf][2] + S[nf][3];
        }
        s0 += __shfl_xor_sync(0xffffffffu, s0, 1);
        s0 += __shfl_xor_sync(0xffffffffu, s0, 2);
        s1 += __shfl_xor_sync(0xffffffffu, s1, 1);
        s1 += __shfl_xor_sync(0xffffffffu, s1, 2);
        lr[0] = lr[0]*c0 + s0;  lr[1] = lr[1]*c1 + s1;
        mr[0] = mn0;            mr[1] = mn1;
#pragma unroll
        for (int nf = 0; nf < 8; ++nf) {
            O[nf][0] *= c0; O[nf][1] *= c0;
            O[nf][2] *= c1; O[nf][3] *= c1;
        }

#pragma unroll
        for (int kg = 0; kg < 4; ++kg) {
            uint32_t P1a[4], P2a[4];
            split2h(S[2*kg][0],   S[2*kg][1],   P1a[0], P2a[0]);
            split2h(S[2*kg][2],   S[2*kg][3],   P1a[1], P2a[1]);
            split2h(S[2*kg+1][0], S[2*kg+1][1], P1a[2], P2a[2]);
            split2h(S[2*kg+1][2], S[2*kg+1][3], P1a[3], P2a[3]);
            const uint32_t vrow = buf + TB
                                + (uint32_t)(kg*16 + (lane & 15))*ROWB
                                + (uint32_t)(lane >> 4)*16;
#pragma unroll
            for (int np = 0; np < 4; ++np) {
                uint32_t v1[4];
                LDSM4T(v1, vrow + np*32);
                uint32_t bA[2] = {v1[0], v1[1]}, bB[2] = {v1[2], v1[3]};
                MMA_F16(O[2*np],   P1a, bA);
                MMA_F16(O[2*np],   P2a, bA);
                MMA_F16(O[2*np+1], P1a, bB);
                MMA_F16(O[2*np+1], P2a, bB);
            }
        }
    }

    float inv0 = 1.f / lr[0], inv1 = 1.f / lr[1];
    int r0 = i0 + w*16 + g;
    size_t base0 = (size_t)(b*SEQ + r0)    *DMODEL + hoff + tg*2;
    size_t base1 = (size_t)(b*SEQ + r0 + 8)*DMODEL + hoff + tg*2;
#pragma unroll
    for (int nf = 0; nf < 8; ++nf) {
        uint32_t h_, l_;
        split2h(O[nf][0]*inv0, O[nf][1]*inv0, h_, l_);
        *(uint32_t*)(g_as1 + base0 + nf*8) = h_;
        *(uint32_t*)(g_as2 + base0 + nf*8) = l_;
        split2h(O[nf][2]*inv1, O[nf][3]*inv1, h_, l_);
        *(uint32_t*)(g_as1 + base1 + nf*8) = h_;
        *(uint32_t*)(g_as2 + base1 + nf*8) = l_;
    }
}

// ---------------------------------------------------------------------------
extern "C" void kernel_launch(void* const* d_in, const int* in_sizes, int n_in,
                              void* d_out, int out_size)
{
    const float* x  = (const float*)d_in[0];
    const float* wq = (const float*)d_in[1];
    const float* wk = (const float*)d_in[2];
    const float* wv = (const float*)d_in[3];
    const float* wo = (const float*)d_in[4];
    float* out = (float*)d_out;

    __half *xs1, *xs2, *as1, *as2;
    cudaGetSymbolAddress((void**)&xs1, g_xs1);
    cudaGetSymbolAddress((void**)&xs2, g_xs2);
    cudaGetSymbolAddress((void**)&as1, g_as1);
    cudaGetSymbolAddress((void**)&as2, g_as2);

    const int shm_gemm = 2 * STAGE_BYTES;   // 98304
    cudaFuncSetAttribute(gemm_mma, cudaFuncAttributeMaxDynamicSharedMemorySize, shm_gemm);

    rope_kernel<<<(SEQ*32 + 255)/256, 256>>>();
    split_kernel<<<(MTOT*DMODEL/4 + 255)/256, 256>>>(x, xs1, xs2, MTOT*DMODEL/4);
    split_w_kernel<<<(WN + 255)/256, 256>>>(wq, wk, wv, wo);

    // fused QKV projection: 24 x 32 CTAs
    gemm_mma<<<dim3(3*DMODEL/128, MTOT/128), 256, shm_gemm>>>(xs1, xs2, nullptr, 1);

    const int shm_attn = 2 * STG;   // 36864
    cudaFuncSetAttribute(attn_mma, cudaFuncAttributeMaxDynamicSharedMemorySize, shm_attn);
    attn_mma<<<dim3(SEQ/64, NH, NB), 128, shm_attn>>>();

    // Wo projection
    gemm_mma<<<dim3(DMODEL/128, MTOT/128), 256, shm_gemm>>>(as1, as2, out, 0);
}

// round 16
// speedup vs baseline: 1.0220x; 1.0220x over previous
#include <cuda_runtime.h>
#include <cuda_fp16.h>
#include <math.h>
#include <stdint.h>

#define DMODEL 1024
#define SEQ    2048
#define NB     2
#define NH     16
#define HD     64
#define MTOT   (NB*SEQ)          // 4096
#define WN     (DMODEL*DMODEL)

// ---------------- scratch (__device__ globals; allocation-free rule) --------
__device__ __align__(16) __half g_xs1[MTOT*DMODEL];
__device__ __align__(16) __half g_xs2[MTOT*DMODEL];
__device__ __align__(16) __half g_as1[MTOT*DMODEL];
__device__ __align__(16) __half g_as2[MTOT*DMODEL];
__device__ __align__(16) __half g_w1[4*WN];          // single fp16 weights
__device__ __align__(16) __half g_q1[MTOT*DMODEL];
__device__ __align__(16) __half g_q2[MTOT*DMODEL];
__device__ __align__(16) __half g_k1[MTOT*DMODEL];   // single fp16 K
__device__ __align__(16) __half g_v1[MTOT*DMODEL];   // single fp16 V
__device__ __align__(16) float2 g_rope[SEQ*32];      // (cos, sin) per (t, d)

// ---------------- PTX helpers ----------------------------------------------
__device__ __forceinline__ uint32_t smem_u32(const void* p) {
    uint32_t a;
    asm("{ .reg .u64 t; cvta.to.shared.u64 t, %1; cvt.u32.u64 %0, t; }"
        : "=r"(a) : "l"(p));
    return a;
}
__device__ __forceinline__ void cp16(uint32_t dst, const void* src) {
    asm volatile("cp.async.cg.shared.global [%0], [%1], 16;" :: "r"(dst), "l"(src));
}
#define CP_COMMIT()  asm volatile("cp.async.commit_group;" ::: "memory")
#define CP_WAIT(n)   asm volatile("cp.async.wait_group %0;" :: "n"(n) : "memory")

#define LDSM4(r, adr) \
    asm volatile("ldmatrix.sync.aligned.m8n8.x4.shared.b16 {%0,%1,%2,%3}, [%4];" \
        : "=r"((r)[0]), "=r"((r)[1]), "=r"((r)[2]), "=r"((r)[3]) : "r"(adr))
#define LDSM4T(r, adr) \
    asm volatile("ldmatrix.sync.aligned.m8n8.x4.trans.shared.b16 {%0,%1,%2,%3}, [%4];" \
        : "=r"((r)[0]), "=r"((r)[1]), "=r"((r)[2]), "=r"((r)[3]) : "r"(adr))

#define MMA_F16(c, a, b) \
    asm volatile("mma.sync.aligned.m16n8k16.row.col.f32.f16.f16.f32 " \
        "{%0,%1,%2,%3}, {%4,%5,%6,%7}, {%8,%9}, {%0,%1,%2,%3};" \
        : "+f"((c)[0]), "+f"((c)[1]), "+f"((c)[2]), "+f"((c)[3]) \
        : "r"((a)[0]), "r"((a)[1]), "r"((a)[2]), "r"((a)[3]), \
          "r"((b)[0]), "r"((b)[1]))

__device__ __forceinline__ uint32_t packh(float a, float b) {
    uint32_t r;
    asm("cvt.rn.f16x2.f32 %0, %1, %2;" : "=r"(r) : "f"(b), "f"(a));
    return r;
}
__device__ __forceinline__ void split2h(float a, float b, uint32_t& hi, uint32_t& lo) {
    hi = packh(a, b);
    float ah, bh;
    asm("{ .reg .f16 h0, h1; mov.b32 {h0, h1}, %2;"
        " cvt.f32.f16 %0, h0; cvt.f32.f16 %1, h1; }"
        : "=f"(ah), "=f"(bh) : "r"(hi));
    lo = packh(a - ah, b - bh);
}

// swizzles
#define SW128X(o) ((o) ^ (((o) >> 3) & 0x70))

// ---------------- fused prep kernel (x-split | w-pack | rope) ---------------
#define NX4   (MTOT*DMODEL/4)     // 1048576 x-split items (float4)
#define NPREP (NX4 + WN + SEQ*32) // + 1048576 w items + 65536 rope items

__global__ __launch_bounds__(256)
void prep_kernel(const float* __restrict__ x,
                 const float* __restrict__ wq, const float* __restrict__ wk,
                 const float* __restrict__ wv, const float* __restrict__ wo)
{
    int i = blockIdx.x * blockDim.x + threadIdx.x;
    if (i < NX4) {
        float4 v = ((const float4*)x)[i];
        uint32_t h0, l0, h1, l1;
        split2h(v.x, v.y, h0, l0);
        split2h(v.z, v.w, h1, l1);
        ((uint2*)g_xs1)[i] = make_uint2(h0, h1);
        ((uint2*)g_xs2)[i] = make_uint2(l0, l1);
    } else if (i < NX4 + WN) {
        int j = i - NX4;
        int wsel = j / (WN/4);
        int off  = j - wsel * (WN/4);
        const float* src = (wsel == 0) ? wq : (wsel == 1) ? wk
                         : (wsel == 2) ? wv : wo;
        float4 v = ((const float4*)src)[off];
        ((uint2*)(g_w1 + (size_t)wsel*WN))[off] =
            make_uint2(packh(v.x, v.y), packh(v.z, v.w));
    } else if (i < NPREP) {
        int j = i - NX4 - WN;
        int t = j >> 5, d = j & 31;
        float invf = exp2f(-(float)d * 0.4152410118609203f);
        float sn, cs;
        sincosf((float)t * invf, &sn, &cs);
        g_rope[j] = make_float2(cs, sn);
    }
}

// ---------------- mma.sync GEMM (round-13 inner loop, verbatim) -------------
#define TILE_BYTES 16384            // 128 rows * 128 B (64 fp16)
#define STAGE_BYTES (3*TILE_BYTES)  // A1, A2, B = 49152

__global__ __launch_bounds__(256, 2)
void gemm_mma(const __half* __restrict__ A1, const __half* __restrict__ A2,
              float* __restrict__ C, int qkv)
{
    extern __shared__ __align__(16) char sm[];
    const uint32_t sb = smem_u32(sm);
    const int tid = threadIdx.x;
    const int lane = tid & 31, wid = tid >> 5;
    const int wm = wid & 3, wn = wid >> 2;
    const int m0 = blockIdx.y << 7;
    const int nglob = blockIdx.x << 7;

    int wsel, n0, mode;
    __half *D1 = nullptr, *D2 = nullptr;
    if (qkv) {
        wsel = nglob >> 10;           // 0=Q,1=K,2=V
        n0   = nglob & 1023;
        mode = wsel + 1;
        D1 = (wsel == 0) ? g_q1 : (wsel == 1) ? g_k1 : g_v1;
        D2 = (wsel == 0) ? g_q2 : nullptr;
    } else {
        wsel = 3; n0 = nglob; mode = 0;
    }
    const __half* B1 = g_w1 + (size_t)wsel * WN;

    float acc[2][8][4];
#pragma unroll
    for (int mf = 0; mf < 2; ++mf)
#pragma unroll
        for (int nf = 0; nf < 8; ++nf)
#pragma unroll
            for (int j = 0; j < 4; ++j) acc[mf][nf][j] = 0.f;

    const int lrow = tid >> 3;
    const int lch  = tid & 7;
    uint32_t st_sw[4];
#pragma unroll
    for (int p = 0; p < 4; ++p)
        st_sw[p] = SW128X((uint32_t)(lrow + p*32) * 128 + (uint32_t)lch * 16);

    auto load_stage = [&](int t, int slot) {
        const int k0 = t << 6;
        const uint32_t base = sb + (uint32_t)slot * STAGE_BYTES;
#pragma unroll
        for (int tile = 0; tile < 3; ++tile) {
            const __half* S = (tile == 0) ? A1 : (tile == 1) ? A2 : B1;
            const int rb = (tile < 2) ? m0 : n0;
#pragma unroll
            for (int p = 0; p < 4; ++p)
                cp16(base + tile * TILE_BYTES + st_sw[p],
                     S + (size_t)(rb + lrow + p*32) * DMODEL + k0 + lch * 8);
        }
    };

    load_stage(0, 0); CP_COMMIT();

    const uint32_t a_row  = (uint32_t)(wm * 32) + (lane & 15);
    const uint32_t a_koff = (uint32_t)(lane >> 4) * 16;
    const uint32_t b_row  = (uint32_t)(wn * 64) + (lane & 7) + ((lane >> 4) & 1) * 8;
    const uint32_t b_koff = (uint32_t)((lane >> 3) & 1) * 16;

    for (int t = 0; t < 16; ++t) {
        CP_WAIT(0);
        __syncthreads();
        if (t < 15) { load_stage(t + 1, (t + 1) & 1); CP_COMMIT(); }

        const uint32_t buf = sb + (uint32_t)(t & 1) * STAGE_BYTES;
#pragma unroll
        for (int ks = 0; ks < 4; ++ks) {
            const uint32_t kbyte = (uint32_t)ks * 32;
            uint32_t A1f[2][4], A2f[2][4];
#pragma unroll
            for (int mf = 0; mf < 2; ++mf) {
                uint32_t o = (a_row + mf*16) * 128 + kbyte + a_koff;
                uint32_t adr = buf + SW128X(o);
                LDSM4(A1f[mf], adr);
                LDSM4(A2f[mf], adr + TILE_BYTES);
            }
#pragma unroll
            for (int nb = 0; nb < 4; ++nb) {
                uint32_t o = (b_row + nb*16) * 128 + kbyte + b_koff;
                uint32_t adr = buf + 2 * TILE_BYTES + SW128X(o);
                uint32_t rB[4];
                LDSM4(rB, adr);
                uint32_t b_a[2] = {rB[0], rB[1]}, b_b[2] = {rB[2], rB[3]};
#pragma unroll
                for (int mf = 0; mf < 2; ++mf) {
                    MMA_F16(acc[mf][2*nb],   A1f[mf], b_a);
                    MMA_F16(acc[mf][2*nb],   A2f[mf], b_a);
                    MMA_F16(acc[mf][2*nb+1], A1f[mf], b_b);
                    MMA_F16(acc[mf][2*nb+1], A2f[mf], b_b);
                }
            }
        }
    }

    // ---- epilogue ----
    const int g = lane >> 2, tg = lane & 3;
    if (mode == 1) {
#pragma unroll
        for (int mf = 0; mf < 2; ++mf)
#pragma unroll
            for (int rh = 0; rh < 2; ++rh) {
                int row = m0 + wm*32 + mf*16 + g + rh*8;
                const float2* rope = g_rope + (size_t)(row & (SEQ - 1)) * 32 + tg*2;
                size_t base = (size_t)row * DMODEL + n0 + wn*64;
#pragma unroll
                for (int nf = 0; nf < 4; ++nf) {
                    float o1[2], o2[2];
#pragma unroll
                    for (int bb = 0; bb < 2; ++bb) {
                        float2 cssn = rope[nf*8 + bb];
                        float v1 = acc[mf][nf][rh*2 + bb];
                        float v2 = acc[mf][nf+4][rh*2 + bb];
                        o1[bb] = (v1*cssn.x - v2*cssn.y) * 0.125f;
                        o2[bb] = (v2*cssn.x + v1*cssn.y) * 0.125f;
                    }
                    uint32_t h_, l_;
                    split2h(o1[0], o1[1], h_, l_);
                    *(uint32_t*)(D1 + base + nf*8 + tg*2) = h_;
                    *(uint32_t*)(D2 + base + nf*8 + tg*2) = l_;
                    split2h(o2[0], o2[1], h_, l_);
                    *(uint32_t*)(D1 + base + nf*8 + tg*2 + 32) = h_;
                    *(uint32_t*)(D2 + base + nf*8 + tg*2 + 32) = l_;
                }
            }
    } else if (mode == 2) {
#pragma unroll
        for (int mf = 0; mf < 2; ++mf)
#pragma unroll
            for (int rh = 0; rh < 2; ++rh) {
                int row = m0 + wm*32 + mf*16 + g + rh*8;
                const float2* rope = g_rope + (size_t)(row & (SEQ - 1)) * 32 + tg*2;
                size_t base = (size_t)row * DMODEL + n0 + wn*64;
#pragma unroll
                for (int nf = 0; nf < 4; ++nf) {
                    float o1[2], o2[2];
#pragma unroll
                    for (int bb = 0; bb < 2; ++bb) {
                        float2 cssn = rope[nf*8 + bb];
                        float v1 = acc[mf][nf][rh*2 + bb];
                        float v2 = acc[mf][nf+4][rh*2 + bb];
                        o1[bb] = v1*cssn.x - v2*cssn.y;
                        o2[bb] = v2*cssn.x + v1*cssn.y;
                    }
                    *(uint32_t*)(D1 + base + nf*8 + tg*2)      = packh(o1[0], o1[1]);
                    *(uint32_t*)(D1 + base + nf*8 + tg*2 + 32) = packh(o2[0], o2[1]);
                }
            }
    } else if (mode == 3) {
#pragma unroll
        for (int mf = 0; mf < 2; ++mf)
#pragma unroll
            for (int rh = 0; rh < 2; ++rh) {
                int row = m0 + wm*32 + mf*16 + g + rh*8;
                size_t base = (size_t)row * DMODEL + n0 + wn*64;
#pragma unroll
                for (int nf = 0; nf < 8; ++nf)
                    *(uint32_t*)(D1 + base + nf*8 + tg*2) =
                        packh(acc[mf][nf][rh*2], acc[mf][nf][rh*2+1]);
            }
    } else {
#pragma unroll
        for (int mf = 0; mf < 2; ++mf)
#pragma unroll
            for (int rh = 0; rh < 2; ++rh) {
                int row = m0 + wm*32 + mf*16 + g + rh*8;
                float* Crow = C + (size_t)row * DMODEL + n0 + wn*64;
#pragma unroll
                for (int nf = 0; nf < 8; ++nf)
                    *(float2*)(Crow + nf*8 + tg*2) =
                        make_float2(acc[mf][nf][rh*2], acc[mf][nf][rh*2 + 1]);
            }
    }
}

// ---------------- tensor-core flash attention (round-13 verbatim) -----------
#define ROWB 144
#define TB   (64*ROWB)      // 9216 per tile
#define STG  (2*TB)         // K1, V1 per stage = 18432

__global__ __launch_bounds__(128)
void attn_mma()
{
    extern __shared__ __align__(16) char sm[];
    const uint32_t sb = smem_u32(sm);
    const int tid = threadIdx.x, lane = tid & 31, w = tid >> 5;
    const int it = gridDim.x - 1 - blockIdx.x;
    const int h = blockIdx.y, b = blockIdx.z;
    const int i0 = it << 6;
    const size_t hoff = (size_t)h * HD;
    const int g = lane >> 2, tg = lane & 3;

#pragma unroll
    for (int p = 0; p < 4; ++p) {
        int id = tid + (p << 7);
        int row = id >> 3, ch = id & 7;
        size_t gi = (size_t)(b*SEQ + i0 + row)*DMODEL + hoff + ch*8;
        uint32_t dst = sb + row*ROWB + ch*16;
        cp16(dst,      g_q1 + gi);
        cp16(dst + TB, g_q2 + gi);
    }
    CP_COMMIT(); CP_WAIT(0); __syncthreads();

    uint32_t Q1f[4][4], Q2f[4][4];
    const uint32_t a_off = (uint32_t)(lane & 15)*ROWB + (uint32_t)(lane >> 4)*16;
#pragma unroll
    for (int kf = 0; kf < 4; ++kf) {
        uint32_t adr = sb + (uint32_t)(w*16)*ROWB + a_off + kf*32;
        LDSM4(Q1f[kf], adr);
        LDSM4(Q2f[kf], adr + TB);
    }
    __syncthreads();

    auto load_kv = [&](int jt) {
        const int j0 = jt << 6;
        const uint32_t base = sb + (uint32_t)(jt & 1)*STG;
#pragma unroll
        for (int p = 0; p < 4; ++p) {
            int id = tid + (p << 7);
            int row = id >> 3, ch = id & 7;
            size_t gi = (size_t)(b*SEQ + j0 + row)*DMODEL + hoff + ch*8;
            uint32_t dst = base + row*ROWB + ch*16;
            cp16(dst,      g_k1 + gi);
            cp16(dst + TB, g_v1 + gi);
        }
    };

    load_kv(0); CP_COMMIT();

    float mr[2] = {-1e30f, -1e30f}, lr[2] = {0.f, 0.f};
    float O[8][4];
#pragma unroll
    for (int nf = 0; nf < 8; ++nf)
#pragma unroll
        for (int j = 0; j < 4; ++j) O[nf][j] = 0.f;

    const int      b_nloc = (lane & 7) + ((lane >> 4) & 1)*8;
    const uint32_t b_koff = (uint32_t)((lane >> 3) & 1)*16;

    for (int jt = 0; jt <= it; ++jt) {
        if (jt < it) { load_kv(jt + 1); CP_COMMIT(); CP_WAIT(1); }
        else         { CP_WAIT(0); }
        __syncthreads();
        const uint32_t buf = sb + (uint32_t)(jt & 1)*STG;

        float S[8][4];
#pragma unroll
        for (int nf = 0; nf < 8; ++nf)
#pragma unroll
            for (int j = 0; j < 4; ++j) S[nf][j] = 0.f;

#pragma unroll
        for (int kf = 0; kf < 4; ++kf) {
            uint32_t K1f[8][2];
#pragma unroll
            for (int nb = 0; nb < 4; ++nb) {
                uint32_t adr = buf + (uint32_t)(nb*16 + b_nloc)*ROWB + kf*32 + b_koff;
                uint32_t r[4];
                LDSM4(r, adr);
                K1f[2*nb][0] = r[0]; K1f[2*nb][1] = r[1];
                K1f[2*nb+1][0] = r[2]; K1f[2*nb+1][1] = r[3];
            }
#pragma unroll
            for (int nf = 0; nf < 8; ++nf) {
                MMA_F16(S[nf], Q1f[kf], K1f[nf]);
                MMA_F16(S[nf], Q2f[kf], K1f[nf]);
            }
        }

        if (jt == it) {
            int r0 = w*16 + g;
#pragma unroll
            for (int nf = 0; nf < 8; ++nf)
#pragma unroll
                for (int j = 0; j < 2; ++j) {
                    int col = nf*8 + tg*2 + j;
                    if (col > r0)     S[nf][j]   = -1e30f;
                    if (col > r0 + 8) S[nf][j+2] = -1e30f;
                }
        }

        float mx0 = -1e30f, mx1 = -1e30f;
#pragma unroll
        for (int nf = 0; nf < 8; ++nf) {
            mx0 = fmaxf(mx0, fmaxf(S[nf][0], S[nf][1]));
            mx1 = fmaxf(mx1, fmaxf(S[nf][2], S[nf][3]));
        }
        mx0 = fmaxf(mx0, __shfl_xor_sync(0xffffffffu, mx0, 1));
        mx0 = fmaxf(mx0, __shfl_xor_sync(0xffffffffu, mx0, 2));
        mx1 = fmaxf(mx1, __shfl_xor_sync(0xffffffffu, mx1, 1));
        mx1 = fmaxf(mx1, __shfl_xor_sync(0xffffffffu, mx1, 2));
        float mn0 = fmaxf(mr[0], mx0), mn1 = fmaxf(mr[1], mx1);
        float c0 = __expf(mr[0] - mn0), c1 = __expf(mr[1] - mn1);
        float s0 = 0.f, s1 = 0.f;
#pragma unroll
        for (int nf = 0; nf < 8; ++nf) {
            S[nf][0] = __expf(S[nf][0] - mn0);
            S[nf][1] = __expf(S[nf][1] - mn0);
            S[nf][2] = __expf(S[nf][2] - mn1);
            S[nf][3] = __expf(S[nf][3] - mn1);
            s0 += S[nf][0] + S[nf][1];
            s1 += S[nf][2] + S[nf][3];
        }
        s0 += __shfl_xor_sync(0xffffffffu, s0, 1);
        s0 += __shfl_xor_sync(0xffffffffu, s0, 2);
        s1 += __shfl_xor_sync(0xffffffffu, s1, 1);
        s1 += __shfl_xor_sync(0xffffffffu, s1, 2);
        lr[0] = lr[0]*c0 + s0;  lr[1] = lr[1]*c1 + s1;
        mr[0] = mn0;            mr[1] = mn1;
#pragma unroll
        for (int nf = 0; nf < 8; ++nf) {
            O[nf][0] *= c0; O[nf][1] *= c0;
            O[nf][2] *= c1; O[nf][3] *= c1;
        }

#pragma unroll
        for (int kg = 0; kg < 4; ++kg) {
            uint32_t P1a[4], P2a[4];
            split2h(S[2*kg][0],   S[2*kg][1],   P1a[0], P2a[0]);
            split2h(S[2*kg][2],   S[2*kg][3],   P1a[1], P2a[1]);
            split2h(S[2*kg+1][0], S[2*kg+1][1], P1a[2], P2a[2]);
            split2h(S[2*kg+1][2], S[2*kg+1][3], P1a[3], P2a[3]);
            const uint32_t vrow = buf + TB
                                + (uint32_t)(kg*16 + (lane & 15))*ROWB
                                + (uint32_t)(lane >> 4)*16;
#pragma unroll
            for (int np = 0; np < 4; ++np) {
                uint32_t v1[4];
                LDSM4T(v1, vrow + np*32);
                uint32_t bA[2] = {v1[0], v1[1]}, bB[2] = {v1[2], v1[3]};
                MMA_F16(O[2*np],   P1a, bA);
                MMA_F16(O[2*np],   P2a, bA);
                MMA_F16(O[2*np+1], P1a, bB);
                MMA_F16(O[2*np+1], P2a, bB);
            }
        }
        __syncthreads();
    }

    float inv0 = 1.f / lr[0], inv1 = 1.f / lr[1];
    int r0 = i0 + w*16 + g;
    size_t base0 = (size_t)(b*SEQ + r0)    *DMODEL + hoff + tg*2;
    size_t base1 = (size_t)(b*SEQ + r0 + 8)*DMODEL + hoff + tg*2;
#pragma unroll
    for (int nf = 0; nf < 8; ++nf) {
        uint32_t h_, l_;
        split2h(O[nf][0]*inv0, O[nf][1]*inv0, h_, l_);
        *(uint32_t*)(g_as1 + base0 + nf*8) = h_;
        *(uint32_t*)(g_as2 + base0 + nf*8) = l_;
        split2h(O[nf][2]*inv1, O[nf][3]*inv1, h_, l_);
        *(uint32_t*)(g_as1 + base1 + nf*8) = h_;
        *(uint32_t*)(g_as2 + base1 + nf*8) = l_;
    }
}

// ---------------------------------------------------------------------------
extern "C" void kernel_launch(void* const* d_in, const int* in_sizes, int n_in,
                              void* d_out, int out_size)
{
    const float* x  = (const float*)d_in[0];
    const float* wq = (const float*)d_in[1];
    const float* wk = (const float*)d_in[2];
    const float* wv = (const float*)d_in[3];
    const float* wo = (const float*)d_in[4];
    float* out = (float*)d_out;

    __half *xs1, *xs2, *as1, *as2;
    cudaGetSymbolAddress((void**)&xs1, g_xs1);
    cudaGetSymbolAddress((void**)&xs2, g_xs2);
    cudaGetSymbolAddress((void**)&as1, g_as1);
    cudaGetSymbolAddress((void**)&as2, g_as2);

    const int shm_gemm = 2 * STAGE_BYTES;   // 98304
    cudaFuncSetAttribute(gemm_mma, cudaFuncAttributeMaxDynamicSharedMemorySize, shm_gemm);

    // fused prep: x split + weight pack + rope table, one launch
    prep_kernel<<<(NPREP + 255)/256, 256>>>(x, wq, wk, wv, wo);

    // fused QKV projection: 24 x 32 CTAs
    gemm_mma<<<dim3(3*DMODEL/128, MTOT/128), 256, shm_gemm>>>(xs1, xs2, nullptr, 1);

    const int shm_attn = 2 * STG;   // 36864
    cudaFuncSetAttribute(attn_mma, cudaFuncAttributeMaxDynamicSharedMemorySize, shm_attn);
    attn_mma<<<dim3(SEQ/64, NH, NB), 128, shm_attn>>>();

    // Wo projection
    gemm_mma<<<dim3(DMODEL/128, MTOT/128), 256, shm_gemm>>>(as1, as2, out, 0);
}